// round 1
// baseline (speedup 1.0000x reference)
#include <cuda_runtime.h>
#include <math.h>

// Problem constants
#define BB     32
#define LDRUG  256
#define LPROT  1024
#define DMODEL 512
#define NH     8
#define DK     64
#define NBH    (BB*NH)   // 256

// ---------------- scratch (device globals; no allocations allowed) ----------
__device__ float g_Qd[(size_t)NBH*LDRUG*DK];    // scaled by a*0.125
__device__ float g_Kd[(size_t)NBH*LDRUG*DK];    // scaled by (1-a)*0.125
__device__ float g_Vd[(size_t)NBH*LDRUG*DK];
__device__ float g_Kp[(size_t)NBH*LPROT*DK];
__device__ float g_Qp[(size_t)NBH*LPROT*DK];
__device__ float g_Vp[(size_t)NBH*LPROT*DK];
__device__ float g_S [(size_t)NBH*LDRUG*LPROT]; // pre-softmax scores
__device__ float g_ctxd[(size_t)BB*LDRUG*DMODEL];
__device__ float g_ctxp[(size_t)BB*LPROT*DMODEL];

// ---------------------------------------------------------------------------
// Generic projection GEMM:  C = f * (A @ W^T + bias)
// A: [M, 512] row-major, W: [512, 512] row-major (out x in), bias: [512]
// headLayout=1: write C[(b*NH+h)*L + l)*64 + c]  (m = b*L+l, n = h*64+c)
// headLayout=0: write C[m*512 + n]
// fmode: 0 -> f=1 ; 1 -> f=sigmoid(*alpha)*0.125 ; 2 -> f=(1-sigmoid(*alpha))*0.125
// Tiling: 128x128x8, 256 threads, 8x8 per thread.
// ---------------------------------------------------------------------------
__global__ void __launch_bounds__(256) proj_gemm_kernel(
    const float* __restrict__ A, const float* __restrict__ W,
    const float* __restrict__ bias, float* __restrict__ C,
    const float* __restrict__ alphap, int fmode, int L, int headLayout)
{
    const int K = 512;
    __shared__ float As[8][128];
    __shared__ float Bs[8][128];

    const int tid = threadIdx.x;
    const int m0  = blockIdx.y * 128;
    const int n0  = blockIdx.x * 128;

    const int lrow = tid >> 1;          // 0..127
    const int lcol = (tid & 1) << 2;    // 0 or 4
    const float* Aload = A + (size_t)(m0 + lrow) * K + lcol;
    const float* Wload = W + (size_t)(n0 + lrow) * K + lcol;

    const int ty = tid >> 4;            // 0..15
    const int tx = tid & 15;            // 0..15

    float acc[8][8];
#pragma unroll
    for (int i = 0; i < 8; i++)
#pragma unroll
        for (int j = 0; j < 8; j++) acc[i][j] = 0.0f;

    for (int k0 = 0; k0 < K; k0 += 8) {
        float4 av = *(const float4*)(Aload + k0);
        float4 wv = *(const float4*)(Wload + k0);
        __syncthreads();
        As[lcol+0][lrow] = av.x; As[lcol+1][lrow] = av.y;
        As[lcol+2][lrow] = av.z; As[lcol+3][lrow] = av.w;
        Bs[lcol+0][lrow] = wv.x; Bs[lcol+1][lrow] = wv.y;
        Bs[lcol+2][lrow] = wv.z; Bs[lcol+3][lrow] = wv.w;
        __syncthreads();
#pragma unroll
        for (int k = 0; k < 8; k++) {
            float4 a0 = *(const float4*)&As[k][ty*8];
            float4 a1 = *(const float4*)&As[k][ty*8+4];
            float4 b0 = *(const float4*)&Bs[k][tx*8];
            float4 b1 = *(const float4*)&Bs[k][tx*8+4];
            float ar[8] = {a0.x,a0.y,a0.z,a0.w,a1.x,a1.y,a1.z,a1.w};
            float br[8] = {b0.x,b0.y,b0.z,b0.w,b1.x,b1.y,b1.z,b1.w};
#pragma unroll
            for (int i = 0; i < 8; i++)
#pragma unroll
                for (int j = 0; j < 8; j++)
                    acc[i][j] = fmaf(ar[i], br[j], acc[i][j]);
        }
    }

    float f = 1.0f;
    if (fmode != 0) {
        float a = 1.0f / (1.0f + expf(-alphap[0]));
        f = (fmode == 1 ? a : (1.0f - a)) * 0.125f;   // 0.125 = 1/sqrt(64)
    }

#pragma unroll
    for (int i = 0; i < 8; i++) {
        int m = m0 + ty*8 + i;
#pragma unroll
        for (int jv = 0; jv < 8; jv += 4) {
            int n = n0 + tx*8 + jv;
            float4 v;
            v.x = f * (acc[i][jv+0] + bias[n+0]);
            v.y = f * (acc[i][jv+1] + bias[n+1]);
            v.z = f * (acc[i][jv+2] + bias[n+2]);
            v.w = f * (acc[i][jv+3] + bias[n+3]);
            size_t idx;
            if (headLayout) {
                int b = m / L, l = m - b * L;
                int h = n >> 6, c = n & 63;
                idx = ((size_t)((b*NH + h)*L + l))*64 + c;
            } else {
                idx = (size_t)m * 512 + n;
            }
            *(float4*)&C[idx] = v;
        }
    }
}

// ---------------------------------------------------------------------------
// Scores: S[bh][q][p] = Qd'[q].Kp[p] + Kd'[q].Qp[p]   (scales pre-folded)
// Per (bh): M=256 (q), N=1024 (p), K=64 per pair (2 pairs).
// Tiling: 64x64, BK=16, 256 threads, 4x4 per thread.
// ---------------------------------------------------------------------------
__global__ void __launch_bounds__(256) scores_kernel(
    const float* __restrict__ Qd, const float* __restrict__ Kp,
    const float* __restrict__ Kd, const float* __restrict__ Qp,
    float* __restrict__ S)
{
    const int bh = blockIdx.z;
    const int q0 = blockIdx.y * 64;
    const int p0 = blockIdx.x * 64;
    const float* Qdb = Qd + (size_t)bh * LDRUG * DK;
    const float* Kdb = Kd + (size_t)bh * LDRUG * DK;
    const float* Kpb = Kp + (size_t)bh * LPROT * DK;
    const float* Qpb = Qp + (size_t)bh * LPROT * DK;

    __shared__ float Qs[16][64];
    __shared__ float Ks[16][64];

    const int tid  = threadIdx.x;
    const int lrow = tid >> 2;          // 0..63
    const int lcol = (tid & 3) << 2;    // 0,4,8,12
    const int ty   = tid >> 4;
    const int tx   = tid & 15;

    float acc[4][4];
#pragma unroll
    for (int i = 0; i < 4; i++)
#pragma unroll
        for (int j = 0; j < 4; j++) acc[i][j] = 0.0f;

#pragma unroll
    for (int pair = 0; pair < 2; pair++) {
        const float* Ab = pair ? Kdb : Qdb;
        const float* Bb = pair ? Qpb : Kpb;
        for (int k0 = 0; k0 < 64; k0 += 16) {
            float4 av = *(const float4*)(Ab + (size_t)(q0 + lrow) * DK + k0 + lcol);
            float4 bv = *(const float4*)(Bb + (size_t)(p0 + lrow) * DK + k0 + lcol);
            __syncthreads();
            Qs[lcol+0][lrow] = av.x; Qs[lcol+1][lrow] = av.y;
            Qs[lcol+2][lrow] = av.z; Qs[lcol+3][lrow] = av.w;
            Ks[lcol+0][lrow] = bv.x; Ks[lcol+1][lrow] = bv.y;
            Ks[lcol+2][lrow] = bv.z; Ks[lcol+3][lrow] = bv.w;
            __syncthreads();
#pragma unroll
            for (int k = 0; k < 16; k++) {
                float4 a = *(const float4*)&Qs[k][ty*4];
                float4 b = *(const float4*)&Ks[k][tx*4];
                float ar[4] = {a.x,a.y,a.z,a.w};
                float br[4] = {b.x,b.y,b.z,b.w};
#pragma unroll
                for (int i = 0; i < 4; i++)
#pragma unroll
                    for (int j = 0; j < 4; j++)
                        acc[i][j] = fmaf(ar[i], br[j], acc[i][j]);
            }
        }
    }

    float* Sb = S + ((size_t)bh * LDRUG + q0) * LPROT + p0;
#pragma unroll
    for (int i = 0; i < 4; i++) {
        float4 v = make_float4(acc[i][0], acc[i][1], acc[i][2], acc[i][3]);
        *(float4*)&Sb[(size_t)(ty*4 + i) * LPROT + tx*4] = v;
    }
}

// ---------------------------------------------------------------------------
// Row softmax over 1024 elements. One block (256 threads) per row.
// ---------------------------------------------------------------------------
__global__ void __launch_bounds__(256) softmax_kernel(
    const float* __restrict__ S, float* __restrict__ out)
{
    const size_t row = blockIdx.x;
    const float* src = S + row * LPROT;
    float* dst = out + row * LPROT;
    const int tid = threadIdx.x;

    float4 v = *(const float4*)(src + tid*4);
    float m = fmaxf(fmaxf(v.x, v.y), fmaxf(v.z, v.w));
#pragma unroll
    for (int o = 16; o > 0; o >>= 1)
        m = fmaxf(m, __shfl_xor_sync(0xFFFFFFFFu, m, o));

    __shared__ float redm[8];
    __shared__ float reds[8];
    if ((tid & 31) == 0) redm[tid >> 5] = m;
    __syncthreads();
    float rm = redm[0];
#pragma unroll
    for (int i = 1; i < 8; i++) rm = fmaxf(rm, redm[i]);

    float e0 = expf(v.x - rm);
    float e1 = expf(v.y - rm);
    float e2 = expf(v.z - rm);
    float e3 = expf(v.w - rm);
    float s = e0 + e1 + e2 + e3;
#pragma unroll
    for (int o = 16; o > 0; o >>= 1)
        s += __shfl_xor_sync(0xFFFFFFFFu, s, o);
    if ((tid & 31) == 0) reds[tid >> 5] = s;
    __syncthreads();
    float tot = 0.0f;
#pragma unroll
    for (int i = 0; i < 8; i++) tot += reds[i];
    float inv = 1.0f / tot;

    float4 o4 = make_float4(e0*inv, e1*inv, e2*inv, e3*inv);
    *(float4*)(dst + tid*4) = o4;
}

// ---------------------------------------------------------------------------
// ctx_d[bh][q][c] = sum_p attn[bh][q][p] * Vp[bh][p][c]
// Per (bh): M=256, N=64, K=1024.  64x64 tile, BK=16, 4x4/thread.
// Output directly in [B, Ld, D] layout.
// ---------------------------------------------------------------------------
__global__ void __launch_bounds__(256) ctxd_kernel(
    const float* __restrict__ attn, const float* __restrict__ Vp,
    float* __restrict__ out)
{
    const int bh = blockIdx.z;
    const int b = bh >> 3, h = bh & 7;
    const int q0 = blockIdx.y * 64;
    const float* Ab = attn + (size_t)bh * LDRUG * LPROT;
    const float* Bb = Vp   + (size_t)bh * LPROT * DK;

    __shared__ float As[16][64];
    __shared__ float Bs[16][64];

    const int tid = threadIdx.x;
    const int ar  = tid >> 2;          // 0..63 (q within tile)
    const int ac  = (tid & 3) << 2;    // 0,4,8,12 (k within tile)
    const int br  = tid >> 4;          // 0..15 (k)
    const int bc  = (tid & 15) << 2;   // 0..60 (c)
    const int ty  = tid >> 4;
    const int tx  = tid & 15;

    float acc[4][4];
#pragma unroll
    for (int i = 0; i < 4; i++)
#pragma unroll
        for (int j = 0; j < 4; j++) acc[i][j] = 0.0f;

    for (int k0 = 0; k0 < LPROT; k0 += 16) {
        float4 av = *(const float4*)(Ab + (size_t)(q0 + ar) * LPROT + k0 + ac);
        float4 bv = *(const float4*)(Bb + (size_t)(k0 + br) * DK + bc);
        __syncthreads();
        As[ac+0][ar] = av.x; As[ac+1][ar] = av.y;
        As[ac+2][ar] = av.z; As[ac+3][ar] = av.w;
        *(float4*)&Bs[br][bc] = bv;
        __syncthreads();
#pragma unroll
        for (int k = 0; k < 16; k++) {
            float4 a = *(const float4*)&As[k][ty*4];
            float4 b = *(const float4*)&Bs[k][tx*4];
            float arr[4] = {a.x,a.y,a.z,a.w};
            float brr[4] = {b.x,b.y,b.z,b.w};
#pragma unroll
            for (int i = 0; i < 4; i++)
#pragma unroll
                for (int j = 0; j < 4; j++)
                    acc[i][j] = fmaf(arr[i], brr[j], acc[i][j]);
        }
    }
#pragma unroll
    for (int i = 0; i < 4; i++) {
        int q = q0 + ty*4 + i;
        float4 v = make_float4(acc[i][0], acc[i][1], acc[i][2], acc[i][3]);
        *(float4*)&out[((size_t)(b*LDRUG + q))*DMODEL + h*64 + tx*4] = v;
    }
}

// ---------------------------------------------------------------------------
// ctx_p[bh][p][c] = sum_q attn[bh][q][p] * Vd[bh][q][c]
// Per (bh): M=1024 (p), N=64, K=256 (q). attn is already [k][m] -> no transpose.
// ---------------------------------------------------------------------------
__global__ void __launch_bounds__(256) ctxp_kernel(
    const float* __restrict__ attn, const float* __restrict__ Vd,
    float* __restrict__ out)
{
    const int bh = blockIdx.z;
    const int b = bh >> 3, h = bh & 7;
    const int p0 = blockIdx.y * 64;
    const float* Ab = attn + (size_t)bh * LDRUG * LPROT;
    const float* Bb = Vd   + (size_t)bh * LDRUG * DK;

    __shared__ float As[16][64];
    __shared__ float Bs[16][64];

    const int tid = threadIdx.x;
    const int r16 = tid >> 4;          // 0..15
    const int c4  = (tid & 15) << 2;   // 0..60
    const int ty  = tid >> 4;
    const int tx  = tid & 15;

    float acc[4][4];
#pragma unroll
    for (int i = 0; i < 4; i++)
#pragma unroll
        for (int j = 0; j < 4; j++) acc[i][j] = 0.0f;

    for (int k0 = 0; k0 < LDRUG; k0 += 16) {
        float4 av = *(const float4*)(Ab + (size_t)(k0 + r16) * LPROT + p0 + c4);
        float4 bv = *(const float4*)(Bb + (size_t)(k0 + r16) * DK + c4);
        __syncthreads();
        *(float4*)&As[r16][c4] = av;   // As[k][m]: direct, attn already transposed view
        *(float4*)&Bs[r16][c4] = bv;
        __syncthreads();
#pragma unroll
        for (int k = 0; k < 16; k++) {
            float4 a = *(const float4*)&As[k][ty*4];
            float4 b = *(const float4*)&Bs[k][tx*4];
            float arr[4] = {a.x,a.y,a.z,a.w};
            float brr[4] = {b.x,b.y,b.z,b.w};
#pragma unroll
            for (int i = 0; i < 4; i++)
#pragma unroll
                for (int j = 0; j < 4; j++)
                    acc[i][j] = fmaf(arr[i], brr[j], acc[i][j]);
        }
    }
#pragma unroll
    for (int i = 0; i < 4; i++) {
        int p = p0 + ty*4 + i;
        float4 v = make_float4(acc[i][0], acc[i][1], acc[i][2], acc[i][3]);
        *(float4*)&out[((size_t)(b*LPROT + p))*DMODEL + h*64 + tx*4] = v;
    }
}

// ---------------------------------------------------------------------------
extern "C" void kernel_launch(void* const* d_in, const int* in_sizes, int n_in,
                              void* d_out, int out_size) {
    const float* drug    = (const float*)d_in[0];
    const float* protein = (const float*)d_in[1];
    const float* Wqd = (const float*)d_in[2];  const float* bqd = (const float*)d_in[3];
    const float* Wkp = (const float*)d_in[4];  const float* bkp = (const float*)d_in[5];
    const float* Wvp = (const float*)d_in[6];  const float* bvp = (const float*)d_in[7];
    const float* Wqp = (const float*)d_in[8];  const float* bqp = (const float*)d_in[9];
    const float* Wkd = (const float*)d_in[10]; const float* bkd = (const float*)d_in[11];
    const float* Wvd = (const float*)d_in[12]; const float* bvd = (const float*)d_in[13];
    const float* alpha = (const float*)d_in[14];
    const float* Wod = (const float*)d_in[15]; const float* bod = (const float*)d_in[16];
    const float* Wop = (const float*)d_in[17]; const float* bop = (const float*)d_in[18];

    float* out      = (float*)d_out;
    float* out_attn = out;
    float* out_cd   = out + (size_t)NBH * LDRUG * LPROT;                    // 67,108,864
    float* out_cp   = out_cd + (size_t)BB * LDRUG * DMODEL;                 // + 4,194,304

    float *qd, *kd, *vd, *kp, *qp, *vp, *sbuf, *cd, *cp;
    cudaGetSymbolAddress((void**)&qd,   g_Qd);
    cudaGetSymbolAddress((void**)&kd,   g_Kd);
    cudaGetSymbolAddress((void**)&vd,   g_Vd);
    cudaGetSymbolAddress((void**)&kp,   g_Kp);
    cudaGetSymbolAddress((void**)&qp,   g_Qp);
    cudaGetSymbolAddress((void**)&vp,   g_Vp);
    cudaGetSymbolAddress((void**)&sbuf, g_S);
    cudaGetSymbolAddress((void**)&cd,   g_ctxd);
    cudaGetSymbolAddress((void**)&cp,   g_ctxp);

    // Projections (head-split layout). Qd gets a*scale, Kd gets (1-a)*scale folded in.
    proj_gemm_kernel<<<dim3(4, 64),  256>>>(drug,    Wqd, bqd, qd, alpha, 1, LDRUG, 1);
    proj_gemm_kernel<<<dim3(4, 64),  256>>>(drug,    Wkd, bkd, kd, alpha, 2, LDRUG, 1);
    proj_gemm_kernel<<<dim3(4, 64),  256>>>(drug,    Wvd, bvd, vd, alpha, 0, LDRUG, 1);
    proj_gemm_kernel<<<dim3(4, 256), 256>>>(protein, Wkp, bkp, kp, alpha, 0, LPROT, 1);
    proj_gemm_kernel<<<dim3(4, 256), 256>>>(protein, Wqp, bqp, qp, alpha, 0, LPROT, 1);
    proj_gemm_kernel<<<dim3(4, 256), 256>>>(protein, Wvp, bvp, vp, alpha, 0, LPROT, 1);

    // Blended scores, then softmax straight into the attn output segment.
    scores_kernel<<<dim3(16, 4, NBH), 256>>>(qd, kp, kd, qp, sbuf);
    softmax_kernel<<<NBH * LDRUG, 256>>>(sbuf, out_attn);

    // Context GEMMs read attn from d_out.
    ctxd_kernel<<<dim3(1, 4,  NBH), 256>>>(out_attn, vp, cd);
    ctxp_kernel<<<dim3(1, 16, NBH), 256>>>(out_attn, vd, cp);

    // Output projections (plain [M,512] layout into d_out segments).
    proj_gemm_kernel<<<dim3(4, 64),  256>>>(cd, Wod, bod, out_cd, alpha, 0, LDRUG, 0);
    proj_gemm_kernel<<<dim3(4, 256), 256>>>(cp, Wop, bop, out_cp, alpha, 0, LPROT, 0);
}

// round 3
// speedup vs baseline: 1.9560x; 1.9560x over previous
#include <cuda_runtime.h>
#include <cstdint>
#include <math.h>

#define BB 32
#define LD 256
#define LP 1024
#define NH 8

// ---- scratch (device globals; allocations are forbidden) ----
__device__ float g_QKd[(size_t)256*LD*128];   // [bh][q][Qd(0:64)|Kd(64:128)] scaled
__device__ float g_KQp[(size_t)256*LP*128];   // [bh][p][Kp(0:64)|Qp(64:128)]
__device__ float g_Vd [(size_t)256*LD*64];
__device__ float g_Vp [(size_t)256*LP*64];
__device__ float g_cd [(size_t)BB*LD*512];
__device__ float g_cp [(size_t)BB*LP*512];

__device__ __forceinline__ float rtf(float x){
    uint32_t u = __float_as_uint(x);
    return __uint_as_float((u + 0x1000u) & 0xFFFFE000u);
}

__device__ __forceinline__ void mma8(float* c, const uint32_t* a, uint32_t b0, uint32_t b1){
    asm volatile("mma.sync.aligned.m16n8k8.row.col.f32.tf32.tf32.f32 "
        "{%0,%1,%2,%3}, {%4,%5,%6,%7}, {%8,%9}, {%0,%1,%2,%3};\n"
        : "+f"(c[0]), "+f"(c[1]), "+f"(c[2]), "+f"(c[3])
        : "r"(a[0]), "r"(a[1]), "r"(a[2]), "r"(a[3]), "r"(b0), "r"(b1));
}

// exp(x) without MUFU: 2^t polynomial, FFMA-only
__device__ __forceinline__ float fexp(float x){
    x = fmaxf(x, -80.0f);
    float t = x * 1.44269504089f;
    float n = rintf(t);
    float f = t - n;
    float p =           1.33336621e-3f;
    p = fmaf(p, f, 9.61011902e-3f);
    p = fmaf(p, f, 5.55036420e-2f);
    p = fmaf(p, f, 2.40226522e-1f);
    p = fmaf(p, f, 6.93147182e-1f);
    p = fmaf(p, f, 1.0f);
    return __int_as_float(__float_as_int(p) + ((int)n << 23));
}

// ---------------------------------------------------------------------------
// Batched TF32 GEMM: out = f * (A @ B^T + bias)
// A: [M, Kdim] rows; B: [N, Kdim] rows (both row-major; rounded to tf32 here).
// Tile 128x128, BK=16, double-buffered, 8 warps (2m x 4n), warp tile 64x32.
// outMode 0: out[gm*ldo + gn]
// outMode 1: out[((b*NH + gn/64)*L + gm%L)*ostride + ooff + gn%64]
// fmode: 0 f=1; 1 f=sigmoid(alpha)/8; 2 f=(1-sigmoid(alpha))/8
// ---------------------------------------------------------------------------
__global__ void __launch_bounds__(256) gemm_tf32(
    const float* __restrict__ A, const float* __restrict__ B,
    const float* __restrict__ bias, float* __restrict__ out,
    const float* __restrict__ alphap,
    int Kdim, long long sA, long long sB, long long sO,
    int fmode, int outMode, int L, int ldo, int ostride, int ooff)
{
    const int z = blockIdx.z;
    A += (size_t)z * sA;  B += (size_t)z * sB;  out += (size_t)z * sO;

    __shared__ float As[2][16][132];   // [k][m]
    __shared__ float Bs[2][16][132];   // [k][n]

    const int tid = threadIdx.x, w = tid >> 5, t = tid & 31;
    const int wm = w & 1, wn = w >> 1;
    const int m0 = blockIdx.y * 128, n0 = blockIdx.x * 128;
    const int li = tid >> 1, lj = (tid & 1) * 8;
    const float* Ap = A + (size_t)(m0 + li) * Kdim + lj;
    const float* Bp = B + (size_t)(n0 + li) * Kdim + lj;

    float acc[4][4][4] = {};
    float4 ra0, ra1, rb0, rb1;
    ra0 = *(const float4*)(Ap);     ra1 = *(const float4*)(Ap + 4);
    rb0 = *(const float4*)(Bp);     rb1 = *(const float4*)(Bp + 4);

    const int NK = Kdim >> 4;
    for (int kt = 0; kt < NK; kt++){
        const int cb = kt & 1;
        {
            float va[8] = {ra0.x,ra0.y,ra0.z,ra0.w,ra1.x,ra1.y,ra1.z,ra1.w};
            float vb[8] = {rb0.x,rb0.y,rb0.z,rb0.w,rb1.x,rb1.y,rb1.z,rb1.w};
#pragma unroll
            for (int l = 0; l < 8; l++){
                As[cb][lj+l][li] = rtf(va[l]);
                Bs[cb][lj+l][li] = rtf(vb[l]);
            }
        }
        if (kt + 1 < NK){
            ra0 = *(const float4*)(Ap + (kt+1)*16);
            ra1 = *(const float4*)(Ap + (kt+1)*16 + 4);
            rb0 = *(const float4*)(Bp + (kt+1)*16);
            rb1 = *(const float4*)(Bp + (kt+1)*16 + 4);
        }
        __syncthreads();
#pragma unroll
        for (int kk = 0; kk < 2; kk++){
            const int k0 = kk*8 + (t & 3);
            uint32_t af[4][4];
#pragma unroll
            for (int mt = 0; mt < 4; mt++){
                int r = wm*64 + mt*16 + (t >> 2);
                af[mt][0] = __float_as_uint(As[cb][k0  ][r  ]);
                af[mt][1] = __float_as_uint(As[cb][k0  ][r+8]);
                af[mt][2] = __float_as_uint(As[cb][k0+4][r  ]);
                af[mt][3] = __float_as_uint(As[cb][k0+4][r+8]);
            }
#pragma unroll
            for (int nt = 0; nt < 4; nt++){
                int n = wn*32 + nt*8 + (t >> 2);
                uint32_t b0 = __float_as_uint(Bs[cb][k0  ][n]);
                uint32_t b1 = __float_as_uint(Bs[cb][k0+4][n]);
#pragma unroll
                for (int mt = 0; mt < 4; mt++) mma8(acc[mt][nt], af[mt], b0, b1);
            }
        }
    }

    float f = 1.0f;
    if (fmode){
        float a = 1.0f / (1.0f + expf(-alphap[0]));
        f = (fmode == 1 ? a : 1.0f - a) * 0.125f;
    }
#pragma unroll
    for (int mt = 0; mt < 4; mt++){
#pragma unroll
        for (int nt = 0; nt < 4; nt++){
            int gn = n0 + wn*32 + nt*8 + (t & 3)*2;
            float bi0 = bias ? bias[gn]   : 0.0f;
            float bi1 = bias ? bias[gn+1] : 0.0f;
#pragma unroll
            for (int hh = 0; hh < 2; hh++){
                int gm = m0 + wm*64 + mt*16 + (t >> 2) + hh*8;
                float o0 = f * (acc[mt][nt][hh*2  ] + bi0);
                float o1 = f * (acc[mt][nt][hh*2+1] + bi1);
                size_t idx;
                if (outMode == 0) idx = (size_t)gm * ldo + gn;
                else {
                    int b = gm / L, l = gm - b * L;
                    idx = ((size_t)((b*NH + (gn >> 6)) * L + l)) * ostride + ooff + (gn & 63);
                }
                *(float2*)&out[idx] = make_float2(o0, o1);
            }
        }
    }
}

// ---------------------------------------------------------------------------
// Row softmax over 1024 elems, in-place capable. fexp (no MUFU).
// ---------------------------------------------------------------------------
__global__ void __launch_bounds__(256) softmax_kernel(
    const float* __restrict__ S, float* __restrict__ out)
{
    const size_t row = blockIdx.x;
    const float* src = S + row * LP;
    float* dst = out + row * LP;
    const int tid = threadIdx.x;

    float4 v = *(const float4*)(src + tid*4);
    float m = fmaxf(fmaxf(v.x, v.y), fmaxf(v.z, v.w));
#pragma unroll
    for (int o = 16; o > 0; o >>= 1) m = fmaxf(m, __shfl_xor_sync(0xFFFFFFFFu, m, o));

    __shared__ float redm[8], reds[8];
    if ((tid & 31) == 0) redm[tid >> 5] = m;
    __syncthreads();
    float rm = redm[0];
#pragma unroll
    for (int i = 1; i < 8; i++) rm = fmaxf(rm, redm[i]);

    float e0 = fexp(v.x - rm), e1 = fexp(v.y - rm);
    float e2 = fexp(v.z - rm), e3 = fexp(v.w - rm);
    float s = e0 + e1 + e2 + e3;
#pragma unroll
    for (int o = 16; o > 0; o >>= 1) s += __shfl_xor_sync(0xFFFFFFFFu, s, o);
    if ((tid & 31) == 0) reds[tid >> 5] = s;
    __syncthreads();
    float tot = 0.0f;
#pragma unroll
    for (int i = 0; i < 8; i++) tot += reds[i];
    float inv = 1.0f / tot;
    *(float4*)(dst + tid*4) = make_float4(e0*inv, e1*inv, e2*inv, e3*inv);
}

// ---------------------------------------------------------------------------
// ctx TF32: out[(b*Lout+gm)*512 + h*64 + gn] = sum_k A·V
// TRANSA=0 (ctx_d): A[m][k] = attn[q][p], K=1024, V=Vp
// TRANSA=1 (ctx_p): A[k][m] = attn[q][p] (m=p,k=q), K=256, V=Vd
// Tile 128m x 64n, BK=16, warp tile 64x16.
// ---------------------------------------------------------------------------
template<int TRANSA>
__global__ void __launch_bounds__(256) ctx_tf32(
    const float* __restrict__ attn, const float* __restrict__ V,
    float* __restrict__ out, int Kdim, int Lout)
{
    const int z = blockIdx.z, b = z >> 3, h = z & 7;
    const int m0 = blockIdx.y * 128;
    const float* A  = attn + (size_t)z * LD * LP;
    const float* Vb = V    + (size_t)z * Kdim * 64;

    __shared__ float As[2][16][132];
    __shared__ float Bs[2][16][68];

    const int tid = threadIdx.x, w = tid >> 5, t = tid & 31;
    const int wm = w & 1, wn = w >> 1;
    const int ai = tid >> 1,  aj = (tid & 1) * 8;     // TRANSA=0 loader
    const int ti = tid >> 4,  tj = (tid & 15) * 8;    // TRANSA=1 loader
    const int bi = tid >> 4,  bj = (tid & 15) * 4;

    float acc[4][2][4] = {};
    float4 r0, r1, rb;
    if (TRANSA == 0){
        r0 = *(const float4*)(A + (size_t)(m0+ai)*LP + aj);
        r1 = *(const float4*)(A + (size_t)(m0+ai)*LP + aj + 4);
    } else {
        r0 = *(const float4*)(A + (size_t)ti*LP + m0 + tj);
        r1 = *(const float4*)(A + (size_t)ti*LP + m0 + tj + 4);
    }
    rb = *(const float4*)(Vb + (size_t)bi*64 + bj);

    const int NK = Kdim >> 4;
    for (int kt = 0; kt < NK; kt++){
        const int cb = kt & 1;
        {
            float va[8] = {r0.x,r0.y,r0.z,r0.w,r1.x,r1.y,r1.z,r1.w};
            if (TRANSA == 0){
#pragma unroll
                for (int l = 0; l < 8; l++) As[cb][aj+l][ai] = rtf(va[l]);
            } else {
#pragma unroll
                for (int l = 0; l < 8; l++) As[cb][ti][tj+l] = rtf(va[l]);
            }
            Bs[cb][bi][bj  ] = rtf(rb.x);  Bs[cb][bi][bj+1] = rtf(rb.y);
            Bs[cb][bi][bj+2] = rtf(rb.z);  Bs[cb][bi][bj+3] = rtf(rb.w);
        }
        if (kt + 1 < NK){
            int k1 = (kt+1)*16;
            if (TRANSA == 0){
                r0 = *(const float4*)(A + (size_t)(m0+ai)*LP + k1 + aj);
                r1 = *(const float4*)(A + (size_t)(m0+ai)*LP + k1 + aj + 4);
            } else {
                r0 = *(const float4*)(A + (size_t)(k1+ti)*LP + m0 + tj);
                r1 = *(const float4*)(A + (size_t)(k1+ti)*LP + m0 + tj + 4);
            }
            rb = *(const float4*)(Vb + (size_t)(k1+bi)*64 + bj);
        }
        __syncthreads();
#pragma unroll
        for (int kk = 0; kk < 2; kk++){
            const int k0 = kk*8 + (t & 3);
            uint32_t af[4][4];
#pragma unroll
            for (int mt = 0; mt < 4; mt++){
                int r = wm*64 + mt*16 + (t >> 2);
                af[mt][0] = __float_as_uint(As[cb][k0  ][r  ]);
                af[mt][1] = __float_as_uint(As[cb][k0  ][r+8]);
                af[mt][2] = __float_as_uint(As[cb][k0+4][r  ]);
                af[mt][3] = __float_as_uint(As[cb][k0+4][r+8]);
            }
#pragma unroll
            for (int nt = 0; nt < 2; nt++){
                int n = wn*16 + nt*8 + (t >> 2);
                uint32_t b0 = __float_as_uint(Bs[cb][k0  ][n]);
                uint32_t b1 = __float_as_uint(Bs[cb][k0+4][n]);
#pragma unroll
                for (int mt = 0; mt < 4; mt++) mma8(acc[mt][nt], af[mt], b0, b1);
            }
        }
    }

#pragma unroll
    for (int mt = 0; mt < 4; mt++){
#pragma unroll
        for (int nt = 0; nt < 2; nt++){
            int gn = wn*16 + nt*8 + (t & 3)*2;
#pragma unroll
            for (int hh = 0; hh < 2; hh++){
                int gm = m0 + wm*64 + mt*16 + (t >> 2) + hh*8;
                size_t idx = ((size_t)(b*Lout + gm))*512 + h*64 + gn;
                *(float2*)&out[idx] = make_float2(acc[mt][nt][hh*2], acc[mt][nt][hh*2+1]);
            }
        }
    }
}

// ---------------------------------------------------------------------------
extern "C" void kernel_launch(void* const* d_in, const int* in_sizes, int n_in,
                              void* d_out, int out_size) {
    const float* drug    = (const float*)d_in[0];
    const float* protein = (const float*)d_in[1];
    const float* Wqd = (const float*)d_in[2];  const float* bqd = (const float*)d_in[3];
    const float* Wkp = (const float*)d_in[4];  const float* bkp = (const float*)d_in[5];
    const float* Wvp = (const float*)d_in[6];  const float* bvp = (const float*)d_in[7];
    const float* Wqp = (const float*)d_in[8];  const float* bqp = (const float*)d_in[9];
    const float* Wkd = (const float*)d_in[10]; const float* bkd = (const float*)d_in[11];
    const float* Wvd = (const float*)d_in[12]; const float* bvd = (const float*)d_in[13];
    const float* alpha = (const float*)d_in[14];
    const float* Wod = (const float*)d_in[15]; const float* bod = (const float*)d_in[16];
    const float* Wop = (const float*)d_in[17]; const float* bop = (const float*)d_in[18];

    float* out      = (float*)d_out;
    float* out_attn = out;
    float* out_cd   = out + (size_t)256*LD*LP;
    float* out_cp   = out_cd + (size_t)BB*LD*512;

    float *qkd, *kqp, *vd, *vp, *cd, *cp;
    cudaGetSymbolAddress((void**)&qkd, g_QKd);
    cudaGetSymbolAddress((void**)&kqp, g_KQp);
    cudaGetSymbolAddress((void**)&vd,  g_Vd);
    cudaGetSymbolAddress((void**)&vp,  g_Vp);
    cudaGetSymbolAddress((void**)&cd,  g_cd);
    cudaGetSymbolAddress((void**)&cp,  g_cp);

    // Projections. Qd gets sig(a)/8, Kd gets (1-sig(a))/8 folded in.
    gemm_tf32<<<dim3(4,64),  256>>>(drug, Wqd, bqd, qkd, alpha, 512,0,0,0, 1,1, LD, 0, 128, 0);
    gemm_tf32<<<dim3(4,64),  256>>>(drug, Wkd, bkd, qkd, alpha, 512,0,0,0, 2,1, LD, 0, 128, 64);
    gemm_tf32<<<dim3(4,64),  256>>>(drug, Wvd, bvd, vd,  alpha, 512,0,0,0, 0,1, LD, 0, 64, 0);
    gemm_tf32<<<dim3(4,256), 256>>>(protein, Wkp, bkp, kqp, alpha, 512,0,0,0, 0,1, LP, 0, 128, 0);
    gemm_tf32<<<dim3(4,256), 256>>>(protein, Wqp, bqp, kqp, alpha, 512,0,0,0, 0,1, LP, 0, 128, 64);
    gemm_tf32<<<dim3(4,256), 256>>>(protein, Wvp, bvp, vp,  alpha, 512,0,0,0, 0,1, LP, 0, 64, 0);

    // Scores: [Qd|Kd] @ [Kp|Qp]^T, K=128, straight into attn region; softmax in place.
    gemm_tf32<<<dim3(8,2,256), 256>>>(qkd, kqp, nullptr, out_attn, alpha,
                                      128, (long long)LD*128, (long long)LP*128,
                                      (long long)LD*LP, 0,0, LD, LP, 0, 0);
    softmax_kernel<<<256*LD, 256>>>(out_attn, out_attn);

    // Contexts (TF32; attn rounded on smem store).
    ctx_tf32<0><<<dim3(1,2,256), 256>>>(out_attn, vp, cd, LP, LD);
    ctx_tf32<1><<<dim3(1,8,256), 256>>>(out_attn, vd, cp, LD, LP);

    // Output projections.
    gemm_tf32<<<dim3(4,64),  256>>>(cd, Wod, bod, out_cd, alpha, 512,0,0,0, 0,0, LD, 512, 0, 0);
    gemm_tf32<<<dim3(4,256), 256>>>(cp, Wop, bop, out_cp, alpha, 512,0,0,0, 0,0, LP, 512, 0, 0);
}

// round 4
// speedup vs baseline: 2.1612x; 1.1049x over previous
#include <cuda_runtime.h>
#include <cstdint>
#include <math.h>

#define BB 32
#define LD 256
#define LP 1024
#define NH 8

// ---- scratch (device globals; allocations are forbidden) ----
__device__ float g_QKd[(size_t)256*LD*128];   // [bh][q][Qd(0:64)|Kd(64:128)] scaled
__device__ float g_KQp[(size_t)256*LP*128];   // [bh][p][Kp(0:64)|Qp(64:128)]
__device__ float g_Vd [(size_t)256*LD*64];
__device__ float g_Vp [(size_t)256*LP*64];
__device__ float g_cd [(size_t)BB*LD*512];
__device__ float g_cp [(size_t)BB*LP*512];

__device__ __forceinline__ float rtf(float x){
    uint32_t u = __float_as_uint(x);
    return __uint_as_float((u + 0x1000u) & 0xFFFFE000u);
}

__device__ __forceinline__ void mma8(float* c, const uint32_t* a, uint32_t b0, uint32_t b1){
    asm volatile("mma.sync.aligned.m16n8k8.row.col.f32.tf32.tf32.f32 "
        "{%0,%1,%2,%3}, {%4,%5,%6,%7}, {%8,%9}, {%0,%1,%2,%3};\n"
        : "+f"(c[0]), "+f"(c[1]), "+f"(c[2]), "+f"(c[3])
        : "r"(a[0]), "r"(a[1]), "r"(a[2]), "r"(a[3]), "r"(b0), "r"(b1));
}

// exp(x) without MUFU: 2^t polynomial, FFMA-only
__device__ __forceinline__ float fexp(float x){
    x = fmaxf(x, -80.0f);
    float t = x * 1.44269504089f;
    float n = rintf(t);
    float f = t - n;
    float p =           1.33336621e-3f;
    p = fmaf(p, f, 9.61011902e-3f);
    p = fmaf(p, f, 5.55036420e-2f);
    p = fmaf(p, f, 2.40226522e-1f);
    p = fmaf(p, f, 6.93147182e-1f);
    p = fmaf(p, f, 1.0f);
    return __int_as_float(__float_as_int(p) + ((int)n << 23));
}

// ---------------------------------------------------------------------------
// Batched TF32 GEMM: out = f * (A @ B^T + bias)
// Tile 128x128, BK=16, double-buffered, 8 warps (2m x 4n), warp tile 64x32.
// smem k-stride 136 (136%32==8) -> fragment loads hit banks 8*(t&3)+(t>>2),
// conflict-free (was 132 -> 4-way conflicts, L1 @ 90%).
// ---------------------------------------------------------------------------
__global__ void __launch_bounds__(256) gemm_tf32(
    const float* __restrict__ A, const float* __restrict__ B,
    const float* __restrict__ bias, float* __restrict__ out,
    const float* __restrict__ alphap,
    int Kdim, long long sA, long long sB, long long sO,
    int fmode, int outMode, int L, int ldo, int ostride, int ooff)
{
    const int z = blockIdx.z;
    A += (size_t)z * sA;  B += (size_t)z * sB;  out += (size_t)z * sO;

    __shared__ float As[2][16][136];   // [k][m]
    __shared__ float Bs[2][16][136];   // [k][n]

    const int tid = threadIdx.x, w = tid >> 5, t = tid & 31;
    const int wm = w & 1, wn = w >> 1;
    const int m0 = blockIdx.y * 128, n0 = blockIdx.x * 128;
    const int li = tid >> 1, lj = (tid & 1) * 8;
    const float* Ap = A + (size_t)(m0 + li) * Kdim + lj;
    const float* Bp = B + (size_t)(n0 + li) * Kdim + lj;

    float acc[4][4][4] = {};
    float4 ra0, ra1, rb0, rb1;
    ra0 = *(const float4*)(Ap);     ra1 = *(const float4*)(Ap + 4);
    rb0 = *(const float4*)(Bp);     rb1 = *(const float4*)(Bp + 4);

    const int NK = Kdim >> 4;
    for (int kt = 0; kt < NK; kt++){
        const int cb = kt & 1;
        {
            float va[8] = {ra0.x,ra0.y,ra0.z,ra0.w,ra1.x,ra1.y,ra1.z,ra1.w};
            float vb[8] = {rb0.x,rb0.y,rb0.z,rb0.w,rb1.x,rb1.y,rb1.z,rb1.w};
#pragma unroll
            for (int l = 0; l < 8; l++){
                As[cb][lj+l][li] = rtf(va[l]);
                Bs[cb][lj+l][li] = rtf(vb[l]);
            }
        }
        if (kt + 1 < NK){
            ra0 = *(const float4*)(Ap + (kt+1)*16);
            ra1 = *(const float4*)(Ap + (kt+1)*16 + 4);
            rb0 = *(const float4*)(Bp + (kt+1)*16);
            rb1 = *(const float4*)(Bp + (kt+1)*16 + 4);
        }
        __syncthreads();
#pragma unroll
        for (int kk = 0; kk < 2; kk++){
            const int k0 = kk*8 + (t & 3);
            uint32_t af[4][4];
#pragma unroll
            for (int mt = 0; mt < 4; mt++){
                int r = wm*64 + mt*16 + (t >> 2);
                af[mt][0] = __float_as_uint(As[cb][k0  ][r  ]);
                af[mt][1] = __float_as_uint(As[cb][k0  ][r+8]);
                af[mt][2] = __float_as_uint(As[cb][k0+4][r  ]);
                af[mt][3] = __float_as_uint(As[cb][k0+4][r+8]);
            }
#pragma unroll
            for (int nt = 0; nt < 4; nt++){
                int n = wn*32 + nt*8 + (t >> 2);
                uint32_t b0 = __float_as_uint(Bs[cb][k0  ][n]);
                uint32_t b1 = __float_as_uint(Bs[cb][k0+4][n]);
#pragma unroll
                for (int mt = 0; mt < 4; mt++) mma8(acc[mt][nt], af[mt], b0, b1);
            }
        }
        __syncthreads();
    }

    float f = 1.0f;
    if (fmode){
        float a = 1.0f / (1.0f + expf(-alphap[0]));
        f = (fmode == 1 ? a : 1.0f - a) * 0.125f;
    }
#pragma unroll
    for (int mt = 0; mt < 4; mt++){
#pragma unroll
        for (int nt = 0; nt < 4; nt++){
            int gn = n0 + wn*32 + nt*8 + (t & 3)*2;
            float bi0 = bias ? bias[gn]   : 0.0f;
            float bi1 = bias ? bias[gn+1] : 0.0f;
#pragma unroll
            for (int hh = 0; hh < 2; hh++){
                int gm = m0 + wm*64 + mt*16 + (t >> 2) + hh*8;
                float o0 = f * (acc[mt][nt][hh*2  ] + bi0);
                float o1 = f * (acc[mt][nt][hh*2+1] + bi1);
                size_t idx;
                if (outMode == 0) idx = (size_t)gm * ldo + gn;
                else {
                    int b = gm / L, l = gm - b * L;
                    idx = ((size_t)((b*NH + (gn >> 6)) * L + l)) * ostride + ooff + (gn & 63);
                }
                *(float2*)&out[idx] = make_float2(o0, o1);
            }
        }
    }
}

// ---------------------------------------------------------------------------
// Row softmax over 1024 elems, in-place capable. fexp (no MUFU).
// ---------------------------------------------------------------------------
__global__ void __launch_bounds__(256) softmax_kernel(
    const float* __restrict__ S, float* __restrict__ out)
{
    const size_t row = blockIdx.x;
    const float* src = S + row * LP;
    float* dst = out + row * LP;
    const int tid = threadIdx.x;

    float4 v = *(const float4*)(src + tid*4);
    float m = fmaxf(fmaxf(v.x, v.y), fmaxf(v.z, v.w));
#pragma unroll
    for (int o = 16; o > 0; o >>= 1) m = fmaxf(m, __shfl_xor_sync(0xFFFFFFFFu, m, o));

    __shared__ float redm[8], reds[8];
    if ((tid & 31) == 0) redm[tid >> 5] = m;
    __syncthreads();
    float rm = redm[0];
#pragma unroll
    for (int i = 1; i < 8; i++) rm = fmaxf(rm, redm[i]);

    float e0 = fexp(v.x - rm), e1 = fexp(v.y - rm);
    float e2 = fexp(v.z - rm), e3 = fexp(v.w - rm);
    float s = e0 + e1 + e2 + e3;
#pragma unroll
    for (int o = 16; o > 0; o >>= 1) s += __shfl_xor_sync(0xFFFFFFFFu, s, o);
    if ((tid & 31) == 0) reds[tid >> 5] = s;
    __syncthreads();
    float tot = 0.0f;
#pragma unroll
    for (int i = 0; i < 8; i++) tot += reds[i];
    float inv = 1.0f / tot;
    *(float4*)(dst + tid*4) = make_float4(e0*inv, e1*inv, e2*inv, e3*inv);
}

// ---------------------------------------------------------------------------
// ctx TF32 (padded 136/72 -> conflict-free fragment loads)
// TRANSA=0 (ctx_d): A[m][k] = attn[q][p], K=1024, V=Vp
// TRANSA=1 (ctx_p): A[k][m] = attn[q][p] (m=p,k=q), K=256, V=Vd
// ---------------------------------------------------------------------------
template<int TRANSA>
__global__ void __launch_bounds__(256) ctx_tf32(
    const float* __restrict__ attn, const float* __restrict__ V,
    float* __restrict__ out, int Kdim, int Lout)
{
    const int z = blockIdx.z, b = z >> 3, h = z & 7;
    const int m0 = blockIdx.y * 128;
    const float* A  = attn + (size_t)z * LD * LP;
    const float* Vb = V    + (size_t)z * Kdim * 64;

    __shared__ float As[2][16][136];
    __shared__ float Bs[2][16][72];

    const int tid = threadIdx.x, w = tid >> 5, t = tid & 31;
    const int wm = w & 1, wn = w >> 1;
    const int ai = tid >> 1,  aj = (tid & 1) * 8;     // TRANSA=0 loader
    const int ti = tid >> 4,  tj = (tid & 15) * 8;    // TRANSA=1 loader
    const int bi = tid >> 4,  bj = (tid & 15) * 4;

    float acc[4][2][4] = {};
    float4 r0, r1, rb;
    if (TRANSA == 0){
        r0 = *(const float4*)(A + (size_t)(m0+ai)*LP + aj);
        r1 = *(const float4*)(A + (size_t)(m0+ai)*LP + aj + 4);
    } else {
        r0 = *(const float4*)(A + (size_t)ti*LP + m0 + tj);
        r1 = *(const float4*)(A + (size_t)ti*LP + m0 + tj + 4);
    }
    rb = *(const float4*)(Vb + (size_t)bi*64 + bj);

    const int NK = Kdim >> 4;
    for (int kt = 0; kt < NK; kt++){
        const int cb = kt & 1;
        {
            float va[8] = {r0.x,r0.y,r0.z,r0.w,r1.x,r1.y,r1.z,r1.w};
            if (TRANSA == 0){
#pragma unroll
                for (int l = 0; l < 8; l++) As[cb][aj+l][ai] = rtf(va[l]);
            } else {
#pragma unroll
                for (int l = 0; l < 8; l++) As[cb][ti][tj+l] = rtf(va[l]);
            }
            Bs[cb][bi][bj  ] = rtf(rb.x);  Bs[cb][bi][bj+1] = rtf(rb.y);
            Bs[cb][bi][bj+2] = rtf(rb.z);  Bs[cb][bi][bj+3] = rtf(rb.w);
        }
        if (kt + 1 < NK){
            int k1 = (kt+1)*16;
            if (TRANSA == 0){
                r0 = *(const float4*)(A + (size_t)(m0+ai)*LP + k1 + aj);
                r1 = *(const float4*)(A + (size_t)(m0+ai)*LP + k1 + aj + 4);
            } else {
                r0 = *(const float4*)(A + (size_t)(k1+ti)*LP + m0 + tj);
                r1 = *(const float4*)(A + (size_t)(k1+ti)*LP + m0 + tj + 4);
            }
            rb = *(const float4*)(Vb + (size_t)(k1+bi)*64 + bj);
        }
        __syncthreads();
#pragma unroll
        for (int kk = 0; kk < 2; kk++){
            const int k0 = kk*8 + (t & 3);
            uint32_t af[4][4];
#pragma unroll
            for (int mt = 0; mt < 4; mt++){
                int r = wm*64 + mt*16 + (t >> 2);
                af[mt][0] = __float_as_uint(As[cb][k0  ][r  ]);
                af[mt][1] = __float_as_uint(As[cb][k0  ][r+8]);
                af[mt][2] = __float_as_uint(As[cb][k0+4][r  ]);
                af[mt][3] = __float_as_uint(As[cb][k0+4][r+8]);
            }
#pragma unroll
            for (int nt = 0; nt < 2; nt++){
                int n = wn*16 + nt*8 + (t >> 2);
                uint32_t b0 = __float_as_uint(Bs[cb][k0  ][n]);
                uint32_t b1 = __float_as_uint(Bs[cb][k0+4][n]);
#pragma unroll
                for (int mt = 0; mt < 4; mt++) mma8(acc[mt][nt], af[mt], b0, b1);
            }
        }
        __syncthreads();
    }

#pragma unroll
    for (int mt = 0; mt < 4; mt++){
#pragma unroll
        for (int nt = 0; nt < 2; nt++){
            int gn = wn*16 + nt*8 + (t & 3)*2;
#pragma unroll
            for (int hh = 0; hh < 2; hh++){
                int gm = m0 + wm*64 + mt*16 + (t >> 2) + hh*8;
                size_t idx = ((size_t)(b*Lout + gm))*512 + h*64 + gn;
                *(float2*)&out[idx] = make_float2(acc[mt][nt][hh*2], acc[mt][nt][hh*2+1]);
            }
        }
    }
}

// ---------------------------------------------------------------------------
extern "C" void kernel_launch(void* const* d_in, const int* in_sizes, int n_in,
                              void* d_out, int out_size) {
    const float* drug    = (const float*)d_in[0];
    const float* protein = (const float*)d_in[1];
    const float* Wqd = (const float*)d_in[2];  const float* bqd = (const float*)d_in[3];
    const float* Wkp = (const float*)d_in[4];  const float* bkp = (const float*)d_in[5];
    const float* Wvp = (const float*)d_in[6];  const float* bvp = (const float*)d_in[7];
    const float* Wqp = (const float*)d_in[8];  const float* bqp = (const float*)d_in[9];
    const float* Wkd = (const float*)d_in[10]; const float* bkd = (const float*)d_in[11];
    const float* Wvd = (const float*)d_in[12]; const float* bvd = (const float*)d_in[13];
    const float* alpha = (const float*)d_in[14];
    const float* Wod = (const float*)d_in[15]; const float* bod = (const float*)d_in[16];
    const float* Wop = (const float*)d_in[17]; const float* bop = (const float*)d_in[18];

    float* out      = (float*)d_out;
    float* out_attn = out;
    float* out_cd   = out + (size_t)256*LD*LP;
    float* out_cp   = out_cd + (size_t)BB*LD*512;

    float *qkd, *kqp, *vd, *vp, *cd, *cp;
    cudaGetSymbolAddress((void**)&qkd, g_QKd);
    cudaGetSymbolAddress((void**)&kqp, g_KQp);
    cudaGetSymbolAddress((void**)&vd,  g_Vd);
    cudaGetSymbolAddress((void**)&vp,  g_Vp);
    cudaGetSymbolAddress((void**)&cd,  g_cd);
    cudaGetSymbolAddress((void**)&cp,  g_cp);

    // Projections. Qd gets sig(a)/8, Kd gets (1-sig(a))/8 folded in.
    gemm_tf32<<<dim3(4,64),  256>>>(drug, Wqd, bqd, qkd, alpha, 512,0,0,0, 1,1, LD, 0, 128, 0);
    gemm_tf32<<<dim3(4,64),  256>>>(drug, Wkd, bkd, qkd, alpha, 512,0,0,0, 2,1, LD, 0, 128, 64);
    gemm_tf32<<<dim3(4,64),  256>>>(drug, Wvd, bvd, vd,  alpha, 512,0,0,0, 0,1, LD, 0, 64, 0);
    gemm_tf32<<<dim3(4,256), 256>>>(protein, Wkp, bkp, kqp, alpha, 512,0,0,0, 0,1, LP, 0, 128, 0);
    gemm_tf32<<<dim3(4,256), 256>>>(protein, Wqp, bqp, kqp, alpha, 512,0,0,0, 0,1, LP, 0, 128, 64);
    gemm_tf32<<<dim3(4,256), 256>>>(protein, Wvp, bvp, vp,  alpha, 512,0,0,0, 0,1, LP, 0, 64, 0);

    // Scores: [Qd|Kd] @ [Kp|Qp]^T, K=128, straight into attn region; softmax in place.
    gemm_tf32<<<dim3(8,2,256), 256>>>(qkd, kqp, nullptr, out_attn, alpha,
                                      128, (long long)LD*128, (long long)LP*128,
                                      (long long)LD*LP, 0,0, LD, LP, 0, 0);
    softmax_kernel<<<256*LD, 256>>>(out_attn, out_attn);

    // Contexts (TF32; attn rounded on smem store).
    ctx_tf32<0><<<dim3(1,2,256), 256>>>(out_attn, vp, cd, LP, LD);
    ctx_tf32<1><<<dim3(1,8,256), 256>>>(out_attn, vd, cp, LD, LP);

    // Output projections.
    gemm_tf32<<<dim3(4,64),  256>>>(cd, Wod, bod, out_cd, alpha, 512,0,0,0, 0,0, LD, 512, 0, 0);
    gemm_tf32<<<dim3(4,256), 256>>>(cp, Wop, bop, out_cp, alpha, 512,0,0,0, 0,0, LP, 512, 0, 0);
}

// round 6
// speedup vs baseline: 2.6816x; 1.2408x over previous
#include <cuda_runtime.h>
#include <cstdint>
#include <math.h>

#define BB 32
#define LD 256
#define LP 1024
#define NH 8

// ---- scratch (device globals; allocations forbidden) ----
__device__ float g_rd [(size_t)BB*LD*512];     // rounded drug
__device__ float g_rp [(size_t)BB*LP*512];     // rounded protein
__device__ float g_W  [(size_t)8*512*512];     // rounded weights
__device__ float g_QKd[(size_t)256*LD*128];    // [bh][q][Qd|Kd] scaled, rounded
__device__ float g_KQp[(size_t)256*LP*128];    // [bh][p][Kp|Qp] rounded
__device__ float g_Vd [(size_t)256*LD*64];     // rounded
__device__ float g_Vp [(size_t)256*LP*64];     // rounded
__device__ float g_aR [(size_t)256*LD*LP];     // rounded attn
__device__ float g_cd [(size_t)BB*LD*512];     // rounded ctx_d
__device__ float g_cp [(size_t)BB*LP*512];     // rounded ctx_p

__device__ __forceinline__ float rtf(float x){
    uint32_t u = __float_as_uint(x);
    return __uint_as_float((u + 0x1000u) & 0xFFFFE000u);
}
__device__ __forceinline__ void cp16(void* s, const void* g){
    uint32_t sa = (uint32_t)__cvta_generic_to_shared(s);
    asm volatile("cp.async.cg.shared.global [%0], [%1], 16;\n" :: "r"(sa), "l"(g));
}
#define CP_COMMIT asm volatile("cp.async.commit_group;\n")
#define CP_WAIT1  asm volatile("cp.async.wait_group 1;\n")

__device__ __forceinline__ void mma8(float* c, const uint32_t* a, uint32_t b0, uint32_t b1){
    asm volatile("mma.sync.aligned.m16n8k8.row.col.f32.tf32.tf32.f32 "
        "{%0,%1,%2,%3}, {%4,%5,%6,%7}, {%8,%9}, {%0,%1,%2,%3};\n"
        : "+f"(c[0]), "+f"(c[1]), "+f"(c[2]), "+f"(c[3])
        : "r"(a[0]), "r"(a[1]), "r"(a[2]), "r"(a[3]), "r"(b0), "r"(b1));
}
__device__ __forceinline__ float fexp(float x){
    x = fmaxf(x, -80.0f);
    float t = x * 1.44269504089f;
    float n = rintf(t);
    float f = t - n;
    float p =           1.33336621e-3f;
    p = fmaf(p, f, 9.61011902e-3f);
    p = fmaf(p, f, 5.55036420e-2f);
    p = fmaf(p, f, 2.40226522e-1f);
    p = fmaf(p, f, 6.93147182e-1f);
    p = fmaf(p, f, 1.0f);
    return __int_as_float(__float_as_int(p) + ((int)n << 23));
}

// ---- tf32 pre-rounding pass ----
__global__ void rnd_kernel(const float4* __restrict__ src, float4* __restrict__ dst, int n4){
    int i = blockIdx.x * blockDim.x + threadIdx.x;
    if (i < n4){
        float4 v = src[i];
        v.x = rtf(v.x); v.y = rtf(v.y); v.z = rtf(v.z); v.w = rtf(v.w);
        dst[i] = v;
    }
}

// ---------------------------------------------------------------------------
// TF32 GEMM, cp.async 2-stage double buffer, static smem (40KB).
// out = f*(A@B^T + bias). A,B pre-rounded to tf32.
// smem stage: A [128 rows][20], B [128 rows][20] -> fragment banks
// 20*(t>>2)+(t&3) all distinct: conflict-free.
// ---------------------------------------------------------------------------
__global__ void __launch_bounds__(256) gemm_ca(
    const float* __restrict__ A, const float* __restrict__ B,
    const float* __restrict__ bias, float* __restrict__ out,
    const float* __restrict__ alphap,
    int Kdim, long long sA, long long sB, long long sO,
    int fmode, int outMode, int L, int ldo, int ostride, int ooff, int roundOut)
{
    __shared__ float smA[2][2560];
    __shared__ float smB[2][2560];
    const int z = blockIdx.z;
    A += (size_t)z * sA;  B += (size_t)z * sB;  out += (size_t)z * sO;

    const int tid = threadIdx.x, w = tid >> 5, t = tid & 31;
    const int wm = w & 1, wn = w >> 1;
    const int m0 = blockIdx.y * 128, n0 = blockIdx.x * 128;
    const int NK = Kdim >> 4;

    auto issue = [&](int kt, int s){
#pragma unroll
        for (int c = tid; c < 512; c += 256){
            int m = c >> 2, kc = (c & 3) << 2;
            cp16(&smA[s][m*20 + kc], A + (size_t)(m0+m)*Kdim + kt*16 + kc);
        }
#pragma unroll
        for (int c = tid; c < 512; c += 256){
            int n = c >> 2, kc = (c & 3) << 2;
            cp16(&smB[s][n*20 + kc], B + (size_t)(n0+n)*Kdim + kt*16 + kc);
        }
    };

    issue(0, 0); CP_COMMIT;

    float acc[4][4][4] = {};
    for (int kt = 0; kt < NK; kt++){
        if (kt + 1 < NK) issue(kt + 1, (kt + 1) & 1);
        CP_COMMIT;             // one group per iteration (possibly empty)
        CP_WAIT1;              // all but newest done -> stage kt ready
        __syncthreads();
        const float* cA = smA[kt & 1];
        const float* cB = smB[kt & 1];
#pragma unroll
        for (int kk = 0; kk < 2; kk++){
            const int k0 = kk*8 + (t & 3);
            uint32_t af[4][4];
#pragma unroll
            for (int mt = 0; mt < 4; mt++){
                int r = wm*64 + mt*16 + (t >> 2);
                af[mt][0] = __float_as_uint(cA[ r     *20 + k0    ]);
                af[mt][1] = __float_as_uint(cA[(r + 8)*20 + k0    ]);
                af[mt][2] = __float_as_uint(cA[ r     *20 + k0 + 4]);
                af[mt][3] = __float_as_uint(cA[(r + 8)*20 + k0 + 4]);
            }
#pragma unroll
            for (int nt = 0; nt < 4; nt++){
                int n = wn*32 + nt*8 + (t >> 2);
                uint32_t b0 = __float_as_uint(cB[n*20 + k0    ]);
                uint32_t b1 = __float_as_uint(cB[n*20 + k0 + 4]);
#pragma unroll
                for (int mt = 0; mt < 4; mt++) mma8(acc[mt][nt], af[mt], b0, b1);
            }
        }
        __syncthreads();
    }

    float f = 1.0f;
    if (fmode){
        float a = 1.0f / (1.0f + expf(-alphap[0]));
        f = (fmode == 1 ? a : 1.0f - a) * 0.125f;
    }
#pragma unroll
    for (int mt = 0; mt < 4; mt++){
#pragma unroll
        for (int nt = 0; nt < 4; nt++){
            int gn = n0 + wn*32 + nt*8 + (t & 3)*2;
            float bi0 = bias ? bias[gn]   : 0.0f;
            float bi1 = bias ? bias[gn+1] : 0.0f;
#pragma unroll
            for (int hh = 0; hh < 2; hh++){
                int gm = m0 + wm*64 + mt*16 + (t >> 2) + hh*8;
                float o0 = f * (acc[mt][nt][hh*2  ] + bi0);
                float o1 = f * (acc[mt][nt][hh*2+1] + bi1);
                if (roundOut){ o0 = rtf(o0); o1 = rtf(o1); }
                size_t idx;
                if (outMode == 0) idx = (size_t)gm * ldo + gn;
                else {
                    int b = gm / L, l = gm - b * L;
                    idx = ((size_t)((b*NH + (gn >> 6)) * L + l)) * ostride + ooff + (gn & 63);
                }
                *(float2*)&out[idx] = make_float2(o0, o1);
            }
        }
    }
}

// ---------------------------------------------------------------------------
// Row softmax over 1024: exact -> dst, tf32-rounded -> dstR.
// ---------------------------------------------------------------------------
__global__ void __launch_bounds__(256) softmax_dual(
    const float* __restrict__ S, float* __restrict__ dst, float* __restrict__ dstR)
{
    const size_t row = blockIdx.x;
    const float* src = S + row * LP;
    const int tid = threadIdx.x;

    float4 v = *(const float4*)(src + tid*4);
    float m = fmaxf(fmaxf(v.x, v.y), fmaxf(v.z, v.w));
#pragma unroll
    for (int o = 16; o > 0; o >>= 1) m = fmaxf(m, __shfl_xor_sync(0xFFFFFFFFu, m, o));
    __shared__ float redm[8], reds[8];
    if ((tid & 31) == 0) redm[tid >> 5] = m;
    __syncthreads();
    float rm = redm[0];
#pragma unroll
    for (int i = 1; i < 8; i++) rm = fmaxf(rm, redm[i]);

    float e0 = fexp(v.x - rm), e1 = fexp(v.y - rm);
    float e2 = fexp(v.z - rm), e3 = fexp(v.w - rm);
    float s = e0 + e1 + e2 + e3;
#pragma unroll
    for (int o = 16; o > 0; o >>= 1) s += __shfl_xor_sync(0xFFFFFFFFu, s, o);
    if ((tid & 31) == 0) reds[tid >> 5] = s;
    __syncthreads();
    float tot = 0.0f;
#pragma unroll
    for (int i = 0; i < 8; i++) tot += reds[i];
    float inv = 1.0f / tot;

    float a0 = e0*inv, a1 = e1*inv, a2 = e2*inv, a3 = e3*inv;
    *(float4*)(dst  + row*LP + tid*4) = make_float4(a0, a1, a2, a3);
    *(float4*)(dstR + row*LP + tid*4) = make_float4(rtf(a0), rtf(a1), rtf(a2), rtf(a3));
}

// ---------------------------------------------------------------------------
// ctx TF32 cp.async 3-stage (static smem). Inputs pre-rounded (g_aR, g_V*).
// TRANSA=0 (ctx_d): A[m][k]=attn[q][p], K=1024; smem As[m(128)][20]
// TRANSA=1 (ctx_p): A[k][m]=attn[q][p] (m=p), K=256; smem As[k(16)][136]
// V: smem Bs[k(16)][72]. Output rounded to scratch.
// ---------------------------------------------------------------------------
template<int TRANSA>
__global__ void __launch_bounds__(256) ctx_ca(
    const float* __restrict__ attn, const float* __restrict__ V,
    float* __restrict__ out, int Kdim, int Lout)
{
    const int ASZ = TRANSA ? 2176 : 2560;       // floats per A stage
    __shared__ float sm[3*2560 + 3*1152];
    float* smB = sm + 3*ASZ;

    const int z = blockIdx.z, b = z >> 3, h = z & 7;
    const int m0 = blockIdx.y * 128;
    const float* A  = attn + (size_t)z * LD * LP;
    const float* Vb = V    + (size_t)z * Kdim * 64;

    const int tid = threadIdx.x, w = tid >> 5, t = tid & 31;
    const int wm = w & 1, wn = w >> 1;
    const int NK = Kdim >> 4;

    auto issue = [&](int kt, int s){
        if (TRANSA == 0){
#pragma unroll
            for (int c = tid; c < 512; c += 256){
                int m = c >> 2, kc = (c & 3) << 2;
                cp16(sm + s*ASZ + m*20 + kc, A + (size_t)(m0+m)*LP + kt*16 + kc);
            }
        } else {
#pragma unroll
            for (int c = tid; c < 512; c += 256){
                int k = c >> 5, m4 = (c & 31) << 2;
                cp16(sm + s*ASZ + k*136 + m4, A + (size_t)(kt*16 + k)*LP + m0 + m4);
            }
        }
        { int c = tid; int k = c >> 4, cc = (c & 15) << 2;
          cp16(smB + s*1152 + k*72 + cc, Vb + (size_t)(kt*16 + k)*64 + cc); }
    };

    issue(0, 0); CP_COMMIT;
    issue(1, 1); CP_COMMIT;

    float acc[4][2][4] = {};
    for (int kt = 0; kt < NK; kt++){
        CP_WAIT1; __syncthreads();
        if (kt + 2 < NK) issue(kt + 2, (kt + 2) % 3);
        CP_COMMIT;
        const float* cA = sm + (kt % 3) * ASZ;
        const float* cB = smB + (kt % 3) * 1152;
#pragma unroll
        for (int kk = 0; kk < 2; kk++){
            const int k0 = kk*8 + (t & 3);
            uint32_t af[4][4];
#pragma unroll
            for (int mt = 0; mt < 4; mt++){
                int r = wm*64 + mt*16 + (t >> 2);
                if (TRANSA == 0){
                    af[mt][0] = __float_as_uint(cA[ r     *20 + k0    ]);
                    af[mt][1] = __float_as_uint(cA[(r + 8)*20 + k0    ]);
                    af[mt][2] = __float_as_uint(cA[ r     *20 + k0 + 4]);
                    af[mt][3] = __float_as_uint(cA[(r + 8)*20 + k0 + 4]);
                } else {
                    af[mt][0] = __float_as_uint(cA[ k0     *136 + r    ]);
                    af[mt][1] = __float_as_uint(cA[ k0     *136 + r + 8]);
                    af[mt][2] = __float_as_uint(cA[(k0 + 4)*136 + r    ]);
                    af[mt][3] = __float_as_uint(cA[(k0 + 4)*136 + r + 8]);
                }
            }
#pragma unroll
            for (int nt = 0; nt < 2; nt++){
                int n = wn*16 + nt*8 + (t >> 2);
                uint32_t b0 = __float_as_uint(cB[ k0     *72 + n]);
                uint32_t b1 = __float_as_uint(cB[(k0 + 4)*72 + n]);
#pragma unroll
                for (int mt = 0; mt < 4; mt++) mma8(acc[mt][nt], af[mt], b0, b1);
            }
        }
        __syncthreads();
    }

#pragma unroll
    for (int mt = 0; mt < 4; mt++){
#pragma unroll
        for (int nt = 0; nt < 2; nt++){
            int gn = wn*16 + nt*8 + (t & 3)*2;
#pragma unroll
            for (int hh = 0; hh < 2; hh++){
                int gm = m0 + wm*64 + mt*16 + (t >> 2) + hh*8;
                size_t idx = ((size_t)(b*Lout + gm))*512 + h*64 + gn;
                *(float2*)&out[idx] = make_float2(rtf(acc[mt][nt][hh*2]), rtf(acc[mt][nt][hh*2+1]));
            }
        }
    }
}

// ---------------------------------------------------------------------------
extern "C" void kernel_launch(void* const* d_in, const int* in_sizes, int n_in,
                              void* d_out, int out_size) {
    const float* drug    = (const float*)d_in[0];
    const float* protein = (const float*)d_in[1];
    const float* Wqd = (const float*)d_in[2];  const float* bqd = (const float*)d_in[3];
    const float* Wkp = (const float*)d_in[4];  const float* bkp = (const float*)d_in[5];
    const float* Wvp = (const float*)d_in[6];  const float* bvp = (const float*)d_in[7];
    const float* Wqp = (const float*)d_in[8];  const float* bqp = (const float*)d_in[9];
    const float* Wkd = (const float*)d_in[10]; const float* bkd = (const float*)d_in[11];
    const float* Wvd = (const float*)d_in[12]; const float* bvd = (const float*)d_in[13];
    const float* alpha = (const float*)d_in[14];
    const float* Wod = (const float*)d_in[15]; const float* bod = (const float*)d_in[16];
    const float* Wop = (const float*)d_in[17]; const float* bop = (const float*)d_in[18];

    float* out      = (float*)d_out;
    float* out_attn = out;
    float* out_cd   = out + (size_t)256*LD*LP;
    float* out_cp   = out_cd + (size_t)BB*LD*512;

    float *rd, *rp, *rw, *qkd, *kqp, *vd, *vp, *aR, *cd, *cp;
    cudaGetSymbolAddress((void**)&rd,  g_rd);
    cudaGetSymbolAddress((void**)&rp,  g_rp);
    cudaGetSymbolAddress((void**)&rw,  g_W);
    cudaGetSymbolAddress((void**)&qkd, g_QKd);
    cudaGetSymbolAddress((void**)&kqp, g_KQp);
    cudaGetSymbolAddress((void**)&vd,  g_Vd);
    cudaGetSymbolAddress((void**)&vp,  g_Vp);
    cudaGetSymbolAddress((void**)&aR,  g_aR);
    cudaGetSymbolAddress((void**)&cd,  g_cd);
    cudaGetSymbolAddress((void**)&cp,  g_cp);

    const int WSZ = 512*512, W4 = WSZ/4;
    // Pre-round inputs and weights into scratch.
    rnd_kernel<<<(BB*LD*512/4 + 255)/256, 256>>>((const float4*)drug,    (float4*)rd, BB*LD*512/4);
    rnd_kernel<<<(BB*LP*512/4 + 255)/256, 256>>>((const float4*)protein, (float4*)rp, BB*LP*512/4);
    const float* Ws[8] = {Wqd, Wkd, Wvd, Wkp, Wqp, Wvp, Wod, Wop};
    for (int i = 0; i < 8; i++)
        rnd_kernel<<<(W4 + 255)/256, 256>>>((const float4*)Ws[i], (float4*)(rw + (size_t)i*WSZ), W4);

    // Projections (rounded outputs). Qd: sig(a)/8; Kd: (1-sig(a))/8.
    gemm_ca<<<dim3(4,64),  256>>>(rd, rw + 0*WSZ, bqd, qkd, alpha, 512,0,0,0, 1,1, LD, 0, 128, 0, 1);
    gemm_ca<<<dim3(4,64),  256>>>(rd, rw + 1*WSZ, bkd, qkd, alpha, 512,0,0,0, 2,1, LD, 0, 128, 64, 1);
    gemm_ca<<<dim3(4,64),  256>>>(rd, rw + 2*WSZ, bvd, vd,  alpha, 512,0,0,0, 0,1, LD, 0, 64, 0, 1);
    gemm_ca<<<dim3(4,256), 256>>>(rp, rw + 3*WSZ, bkp, kqp, alpha, 512,0,0,0, 0,1, LP, 0, 128, 0, 1);
    gemm_ca<<<dim3(4,256), 256>>>(rp, rw + 4*WSZ, bqp, kqp, alpha, 512,0,0,0, 0,1, LP, 0, 128, 64, 1);
    gemm_ca<<<dim3(4,256), 256>>>(rp, rw + 5*WSZ, bvp, vp,  alpha, 512,0,0,0, 0,1, LP, 0, 64, 0, 1);

    // Scores: [Qd|Kd]@[Kp|Qp]^T, K=128, exact into attn region; softmax dual-write.
    gemm_ca<<<dim3(8,2,256), 256>>>(qkd, kqp, nullptr, out_attn, alpha,
                                    128, (long long)LD*128, (long long)LP*128,
                                    (long long)LD*LP, 0,0, LD, LP, 0, 0, 0);
    softmax_dual<<<256*LD, 256>>>(out_attn, out_attn, aR);

    // Contexts from rounded attn + rounded V, rounded outputs.
    ctx_ca<0><<<dim3(1,2,256), 256>>>(aR, vp, cd, LP, LD);
    ctx_ca<1><<<dim3(1,8,256), 256>>>(aR, vd, cp, LD, LP);

    // Output projections (exact into d_out).
    gemm_ca<<<dim3(4,64),  256>>>(cd, rw + 6*WSZ, bod, out_cd, alpha, 512,0,0,0, 0,0, LD, 512, 0, 0, 0);
    gemm_ca<<<dim3(4,256), 256>>>(cp, rw + 7*WSZ, bop, out_cp, alpha, 512,0,0,0, 0,0, LP, 512, 0, 0, 0);
}